// round 8
// baseline (speedup 1.0000x reference)
#include <cuda_runtime.h>
#include <math.h>

// loss = sum_c logdet(G_c + 0.5 I_128) - logdet(G + 0.5 I_128) + 1920*ln2
// where G_c = F_c^T F_c (per-class 128x128 Gram), G = sum_c G_c.
// Derivation: det(sI_m + F F^T) = s^(m-k) det(sI_k + F^T F).

#define MF 1536
#define KD 128
#define NC 16
#define NCHUNK 6
#define RPC (MF / NCHUNK)   // 256 rows per chunk

// slot NC holds the total Gram (sum over classes).
// 16-byte alignment REQUIRED: accessed via red.global.add.v4.f32 and float4*.
__device__ __align__(16) float g_gram[NC + 1][KD][KD];
__device__ float g_ld[NC + 1];

__device__ __forceinline__ void red_add_v4(float* p, float x, float y, float z, float w) {
    asm volatile("red.global.add.v4.f32 [%0], {%1, %2, %3, %4};"
                 :: "l"(p), "f"(x), "f"(y), "f"(z), "f"(w) : "memory");
}

// ---------------------------------------------------------------------------
// Kernel 0: zero the accumulator (device globals persist across graph replays).
// ---------------------------------------------------------------------------
__global__ void zero_kernel() {
    float4* p = (float4*)&g_gram[0][0][0];
    int n = (NC + 1) * KD * KD / 4;   // 69632 float4
    for (int t = blockIdx.x * blockDim.x + threadIdx.x; t < n; t += gridDim.x * blockDim.x)
        p[t] = make_float4(0.f, 0.f, 0.f, 0.f);
}

// ---------------------------------------------------------------------------
// Kernel 1: per-class partial Grams over a 256-row chunk; vector-red into
// g_gram[class] AND g_gram[NC] (total). grid = (NCHUNK, NC), 256 threads,
// each thread owns an 8x8 output tile.
// ---------------------------------------------------------------------------
__global__ __launch_bounds__(256) void gram_kernel(const float* __restrict__ feats,
                                                   const int* __restrict__ labels) {
    const int chunk = blockIdx.x;
    const int c     = blockIdx.y;
    const int tid   = threadIdx.x;
    const int ty    = tid >> 4;
    const int tx    = tid & 15;
    const int base  = chunk * RPC;

    __shared__ int   s_idx[RPC];
    __shared__ int   s_cnt;
    __shared__ __align__(16) float s_rows[8][KD];

    if (tid == 0) s_cnt = 0;
    __syncthreads();
    {   // one label per thread (RPC == blockDim.x)
        int m = base + tid;
        if (labels[m] == c) {
            int p = atomicAdd(&s_cnt, 1);
            s_idx[p] = m;
        }
    }
    __syncthreads();
    const int cnt = s_cnt;

    float acc[8][8];
#pragma unroll
    for (int a = 0; a < 8; a++)
#pragma unroll
        for (int b = 0; b < 8; b++) acc[a][b] = 0.f;

    for (int rb = 0; rb < cnt; rb += 8) {
        __syncthreads();   // s_rows reuse guard
        {   // 8 rows * 128 floats = 256 float4, one per thread (zero-pad tail rows)
            int r  = tid >> 5;          // 0..7
            int c4 = tid & 31;          // float4 col
            float4 v = make_float4(0.f, 0.f, 0.f, 0.f);
            if (rb + r < cnt)
                v = ((const float4*)(feats + s_idx[rb + r] * KD))[c4];
            ((float4*)&s_rows[r][0])[c4] = v;
        }
        __syncthreads();
#pragma unroll
        for (int r = 0; r < 8; r++) {
            float fa[8], fb[8];
#pragma unroll
            for (int a = 0; a < 8; a++) fa[a] = s_rows[r][ty * 8 + a];
#pragma unroll
            for (int b = 0; b < 8; b++) fb[b] = s_rows[r][tx * 8 + b];
#pragma unroll
            for (int a = 0; a < 8; a++)
#pragma unroll
                for (int b = 0; b < 8; b++)
                    acc[a][b] = fmaf(fa[a], fb[b], acc[a][b]);
        }
    }

#pragma unroll
    for (int a = 0; a < 8; a++) {
        int row = ty * 8 + a;
#pragma unroll
        for (int b4 = 0; b4 < 2; b4++) {
            int col = tx * 8 + b4 * 4;
            float x = acc[a][b4 * 4 + 0], y = acc[a][b4 * 4 + 1];
            float z = acc[a][b4 * 4 + 2], w = acc[a][b4 * 4 + 3];
            red_add_v4(&g_gram[c][row][col],  x, y, z, w);
            red_add_v4(&g_gram[NC][row][col], x, y, z, w);
        }
    }
}

// ---------------------------------------------------------------------------
// Kernel 2: Cholesky-pivot logdet of 17 SPD 128x128 matrices. Packed lower
// triangle in shared (conflict-free: triangular row bases mod 32 permute
// banks). 512 threads = 4 j-stripes per row. ONE barrier per iteration:
//   A[i][j] -= (A[i][k] * rcp(A[k][k])) * A[j][k]   (column k never rescaled)
// Final diagonal holds the pivots; logdet = sum log(pivot).
// ---------------------------------------------------------------------------
__global__ __launch_bounds__(512) void chol_kernel() {
    const int b   = blockIdx.x;
    const int tid = threadIdx.x;
    const int i   = tid & 127;   // owned matrix row
    const int h   = tid >> 7;    // 0..3 stripe

    __shared__ float s_tri[KD * (KD + 1) / 2];
    __shared__ float s_red[4];

    const int rowbase = (i * (i + 1)) >> 1;

    // Coalesced load of the full square; keep lower triangle, +0.5 diagonal.
    for (int t = tid; t < KD * KD; t += 512) {
        int r = t >> 7, jj = t & 127;
        if (jj <= r)
            s_tri[((r * (r + 1)) >> 1) + jj] = g_gram[b][r][jj] + (jj == r ? 0.5f : 0.f);
    }
    __syncthreads();

    int dk = 0;                       // diag(k) = k*(k+3)/2
    for (int k = 0; k < KD - 1; k++) {
        float piv = s_tri[dk];        // broadcast
        float inv;
        asm("rcp.approx.f32 %0, %1;" : "=f"(inv) : "f"(piv));
        if (i > k) {
            const float aik = s_tri[rowbase + k] * inv;
            for (int j = k + 1 + h; j <= i; j += 4)
                s_tri[rowbase + j] -= aik * s_tri[((j * (j + 1)) >> 1) + k];
        }
        __syncthreads();
        dk += k + 2;
    }

    // logdet = sum_k log(final diag)
    if (h == 0) {
        float v = logf(s_tri[rowbase + i]);
#pragma unroll
        for (int o = 16; o > 0; o >>= 1)
            v += __shfl_xor_sync(0xffffffffu, v, o);
        if ((i & 31) == 0) s_red[i >> 5] = v;
    }
    __syncthreads();
    if (tid == 0) g_ld[b] = s_red[0] + s_red[1] + s_red[2] + s_red[3];
}

// ---------------------------------------------------------------------------
// Kernel 3: final scalar.
// ---------------------------------------------------------------------------
__global__ void finalize_kernel(float* __restrict__ out) {
    float s = 0.f;
#pragma unroll
    for (int c = 0; c < NC; c++) s += g_ld[c];
    s -= g_ld[NC];
    out[0] = s + 1920.0f * 0.69314718055994530942f;
}

extern "C" void kernel_launch(void* const* d_in, const int* in_sizes, int n_in,
                              void* d_out, int out_size) {
    const float* feats  = (const float*)d_in[0];
    const int*   labels = (const int*)d_in[1];
    // d_in[2] = ious: unused (reference uses coef = ones_like(ious))

    zero_kernel<<<68, 1024>>>();
    gram_kernel<<<dim3(NCHUNK, NC), 256>>>(feats, labels);
    chol_kernel<<<NC + 1, 512>>>();
    finalize_kernel<<<1, 1>>>((float*)d_out);
}

// round 9
// speedup vs baseline: 2.8682x; 2.8682x over previous
#include <cuda_runtime.h>
#include <math.h>

// loss = sum_c logdet(G_c + 0.5 I_128) - logdet(G + 0.5 I_128) + 1920*ln2
// where G_c = F_c^T F_c (per-class 128x128 Gram), G = sum_c G_c.
// Derivation: det(sI_m + F F^T) = s^(m-k) det(sI_k + F^T F).

#define MF 1536
#define KD 128
#define NC 16
#define NCHUNK 6
#define RPC (MF / NCHUNK)   // 256 rows per chunk

// slot NC holds the total Gram. 16B alignment required (red.v4 / float4).
__device__ __align__(16) float g_gram[NC + 1][KD][KD];

__device__ __forceinline__ void red_add_v4(float* p, float x, float y, float z, float w) {
    asm volatile("red.global.add.v4.f32 [%0], {%1, %2, %3, %4};"
                 :: "l"(p), "f"(x), "f"(y), "f"(z), "f"(w) : "memory");
}

// ---------------------------------------------------------------------------
// Kernel 0: zero the Gram accumulator (device globals persist across graph
// replays) and write the constant bias into the output scalar.
// ---------------------------------------------------------------------------
__global__ void zero_kernel(float* __restrict__ out) {
    if (blockIdx.x == 0 && threadIdx.x == 0)
        out[0] = 1920.0f * 0.69314718055994530942f;
    float4* p = (float4*)&g_gram[0][0][0];
    int n = (NC + 1) * KD * KD / 4;
    for (int t = blockIdx.x * blockDim.x + threadIdx.x; t < n; t += gridDim.x * blockDim.x)
        p[t] = make_float4(0.f, 0.f, 0.f, 0.f);
}

// ---------------------------------------------------------------------------
// Kernel 1: per-class partial Grams over a 256-row chunk; vector-red into
// g_gram[class] AND g_gram[NC] (total). grid=(NCHUNK,NC), 256 threads,
// each thread owns an 8x8 output tile.
// ---------------------------------------------------------------------------
__global__ __launch_bounds__(256) void gram_kernel(const float* __restrict__ feats,
                                                   const int* __restrict__ labels) {
    const int chunk = blockIdx.x;
    const int c     = blockIdx.y;
    const int tid   = threadIdx.x;
    const int ty    = tid >> 4;
    const int tx    = tid & 15;
    const int base  = chunk * RPC;

    __shared__ int   s_idx[RPC];
    __shared__ int   s_cnt;
    __shared__ __align__(16) float s_rows[8][KD];

    if (tid == 0) s_cnt = 0;
    __syncthreads();
    {
        int m = base + tid;                 // RPC == blockDim.x
        if (labels[m] == c) {
            int p = atomicAdd(&s_cnt, 1);
            s_idx[p] = m;
        }
    }
    __syncthreads();
    const int cnt = s_cnt;

    float acc[8][8];
#pragma unroll
    for (int a = 0; a < 8; a++)
#pragma unroll
        for (int b = 0; b < 8; b++) acc[a][b] = 0.f;

    for (int rb = 0; rb < cnt; rb += 8) {
        __syncthreads();
        {
            int r  = tid >> 5;
            int c4 = tid & 31;
            float4 v = make_float4(0.f, 0.f, 0.f, 0.f);
            if (rb + r < cnt)
                v = ((const float4*)(feats + s_idx[rb + r] * KD))[c4];
            ((float4*)&s_rows[r][0])[c4] = v;
        }
        __syncthreads();
#pragma unroll
        for (int r = 0; r < 8; r++) {
            float fa[8], fb[8];
#pragma unroll
            for (int a = 0; a < 8; a++) fa[a] = s_rows[r][ty * 8 + a];
#pragma unroll
            for (int b = 0; b < 8; b++) fb[b] = s_rows[r][tx * 8 + b];
#pragma unroll
            for (int a = 0; a < 8; a++)
#pragma unroll
                for (int b = 0; b < 8; b++)
                    acc[a][b] = fmaf(fa[a], fb[b], acc[a][b]);
        }
    }

#pragma unroll
    for (int a = 0; a < 8; a++) {
        int row = ty * 8 + a;
#pragma unroll
        for (int b4 = 0; b4 < 2; b4++) {
            int col = tx * 8 + b4 * 4;
            float x = acc[a][b4 * 4 + 0], y = acc[a][b4 * 4 + 1];
            float z = acc[a][b4 * 4 + 2], w = acc[a][b4 * 4 + 3];
            red_add_v4(&g_gram[c][row][col],  x, y, z, w);
            red_add_v4(&g_gram[NC][row][col], x, y, z, w);
        }
    }
}

// ---------------------------------------------------------------------------
// Kernel 2: logdet of 17 SPD 128x128 matrices via symmetric Gaussian
// elimination with REGISTER-RESIDENT rows. Thread (i,h) (i=tid&127, h=tid>>7)
// holds row i, columns [32h, 32h+32) in 32 registers. Per step k, row k is
// published to a parity-double-buffered shared array; one barrier; then every
// active thread (i>k) does:  r[t] -= (s_row[i]*rcp(s_row[k])) * s_row[32h+t]
// fully unrolled on registers (trailing block symmetry: A[i][k] = A[k][i]).
// Below-diagonal entries self-annihilate at their own step. logdet = sum of
// log(pivots). Each block atomicAdds +/- its logdet into out[0].
// ---------------------------------------------------------------------------
__global__ __launch_bounds__(512) void chol_kernel(float* __restrict__ out) {
    const int b   = blockIdx.x;
    const int tid = threadIdx.x;
    const int i   = tid & 127;   // owned matrix row
    const int h   = tid >> 7;    // segment: columns [32h, 32h+32)

    __shared__ __align__(16) float s_row[2][KD];
    __shared__ float s_piv[KD];
    __shared__ float s_red[4];

    // Load this thread's row segment (full square, symmetric), +0.5 diagonal.
    float r[32];
    {
        const float4* src = (const float4*)&g_gram[b][i][32 * h];
#pragma unroll
        for (int q = 0; q < 8; q++) {
            float4 v = src[q];
            r[4 * q + 0] = v.x; r[4 * q + 1] = v.y;
            r[4 * q + 2] = v.z; r[4 * q + 3] = v.w;
        }
#pragma unroll
        for (int t = 0; t < 32; t++)
            if (32 * h + t == i) r[t] += 0.5f;
    }

    for (int k = 0; k < KD; k++) {
        const int par = k & 1;
        if (i == k) {               // 4 publisher threads write row k
            float4* dst = (float4*)&s_row[par][32 * h];
#pragma unroll
            for (int q = 0; q < 8; q++)
                dst[q] = make_float4(r[4 * q + 0], r[4 * q + 1],
                                     r[4 * q + 2], r[4 * q + 3]);
        }
        __syncthreads();
        if (tid == 0) s_piv[k] = s_row[par][k];
        if (i > k) {
            float piv = s_row[par][k];         // broadcast
            float inv;
            asm("rcp.approx.f32 %0, %1;" : "=f"(inv) : "f"(piv));
            const float naik = -s_row[par][i] * inv;   // -A[i][k]/A[k][k]
            const float4* col = (const float4*)&s_row[par][32 * h];
#pragma unroll
            for (int q = 0; q < 8; q++) {
                float4 cv = col[q];
                r[4 * q + 0] = fmaf(naik, cv.x, r[4 * q + 0]);
                r[4 * q + 1] = fmaf(naik, cv.y, r[4 * q + 1]);
                r[4 * q + 2] = fmaf(naik, cv.z, r[4 * q + 2]);
                r[4 * q + 3] = fmaf(naik, cv.w, r[4 * q + 3]);
            }
        }
    }
    __syncthreads();

    // logdet = sum log(pivots); 128 parallel logs + warp/smem reduction.
    if (h == 0) {
        float v = logf(s_piv[i]);
#pragma unroll
        for (int o = 16; o > 0; o >>= 1)
            v += __shfl_xor_sync(0xffffffffu, v, o);
        if ((i & 31) == 0) s_red[i >> 5] = v;
    }
    __syncthreads();
    if (tid == 0) {
        float ld = s_red[0] + s_red[1] + s_red[2] + s_red[3];
        atomicAdd(out, (b < NC) ? ld : -ld);
    }
}

extern "C" void kernel_launch(void* const* d_in, const int* in_sizes, int n_in,
                              void* d_out, int out_size) {
    const float* feats  = (const float*)d_in[0];
    const int*   labels = (const int*)d_in[1];
    // d_in[2] = ious: unused (reference uses coef = ones_like(ious))
    float* out = (float*)d_out;

    zero_kernel<<<68, 1024>>>(out);
    gram_kernel<<<dim3(NCHUNK, NC), 256>>>(feats, labels);
    chol_kernel<<<NC + 1, 512>>>(out);
}